// round 9
// baseline (speedup 1.0000x reference)
#include <cuda_runtime.h>
#include <math.h>

#define MDIM 512
#define LDIM 31
#define CTOT 542                 // MDIM + LDIM - 1
#define NX   1024
#define ROWE (NX * LDIM)         // 31744 floats per input row strip
#define XCE  (MDIM * LDIM)       // 15872 floats per H/out row strip
#define XC4  (XCE / 4)           // 3968 float4 per row

#define WC     64                // output columns per tile
#define NTILE  (MDIM / WC)       // 8
#define WCOLS  (2 * WC + 2)      // 130 input cols per window
#define YLEN   94                // outputs per tile (WC + LDIM - 1)
#define YPAD   96

// Static scratch
__device__ float g_ynp[NTILE * MDIM * YPAD]; // per-tile partial yn
__device__ float g_yn[MDIM * CTOT];
__device__ float g_rmax1[MDIM];
__device__ float g_rmax2[MDIM];

__device__ __forceinline__ float blockReduceMax(float v, float* sred) {
    __syncthreads();
    int lane = threadIdx.x & 31, wid = threadIdx.x >> 5;
    int nw = blockDim.x >> 5;
    #pragma unroll
    for (int o = 16; o; o >>= 1) v = fmaxf(v, __shfl_xor_sync(0xffffffffu, v, o));
    if (lane == 0) sred[wid] = v;
    __syncthreads();
    if (wid == 0) {
        float x = (lane < nw) ? sred[lane] : -INFINITY;
        #pragma unroll
        for (int o = 16; o; o >>= 1) x = fmaxf(x, __shfl_xor_sync(0xffffffffu, x, o));
        if (lane == 0) sred[0] = x;
    }
    __syncthreads();
    return sred[0];
}

// ---------------------------------------------------------------------------
// Forward: one block per (tile, row). X loads are evict-first streaming
// (read-once data must not evict H from L2); H loads use default policy so
// H is L2-resident for the backward kernels.
// ---------------------------------------------------------------------------
__global__ void __launch_bounds__(256, 6) k_fwd(const float* __restrict__ X,
                                                const float* __restrict__ H) {
    __shared__ float sLam[WCOLS * 32];   // 130 x 32 = 16.25 KB
    __shared__ float sP[WC * 33];        // 64 x 33 = 8.25 KB (conflict-free skew)

    const int t = blockIdx.x, r = blockIdx.y;
    const int tid = threadIdx.x;
    const int lane = tid & 31, warp = tid >> 5;     // 8 warps
    const int c0 = t * WC;
    const int baseCol = 2 * c0 - 1;

    // Row-resize taps ([1/8,3/8,3/8,1/8], renormalized at edges)
    float w0, w1, w2, w3; int i0, i1, i2, i3;
    if (r == 0) {
        w0 = 0.f;     w1 = 3.f/7.f; w2 = 3.f/7.f; w3 = 1.f/7.f;
        i0 = 0; i1 = 0; i2 = 1; i3 = 2;
    } else if (r == MDIM - 1) {
        w0 = 1.f/7.f; w1 = 3.f/7.f; w2 = 3.f/7.f; w3 = 0.f;
        i0 = 2*r - 1; i1 = 2*r; i2 = 2*r + 1; i3 = i2;
    } else {
        w0 = 0.125f;  w1 = 0.375f;  w2 = 0.375f;  w3 = 0.125f;
        i0 = 2*r - 1; i1 = 2*r; i2 = 2*r + 1; i3 = 2*r + 2;
    }
    const float* X0 = X + (size_t)i0 * ROWE;
    const float* X1 = X + (size_t)i1 * ROWE;
    const float* X2p = X + (size_t)i2 * ROWE;
    const float* X3 = X + (size_t)i3 * ROWE;
    const float* Hr = H + (size_t)r * XCE;

    // Phase A: row-combine + lambda-conv via warp shuffles (lane = lambda idx).
    for (int col = warp; col < WCOLS; col += 8) {
        int ic = baseCol + col;
        float x = 0.f;
        if (lane < LDIM && ic >= 0 && ic < NX) {
            int g = ic * LDIM + lane;
            x = w0 * __ldcs(X0 + g) + w1 * __ldcs(X1 + g)
              + w2 * __ldcs(X2p + g) + w3 * __ldcs(X3 + g);
        }
        float xm = __shfl_up_sync(0xffffffffu, x, 1);
        float xp = __shfl_down_sync(0xffffffffu, x, 1);
        float v = 0.5f * x;
        if (lane > 0)         v += 0.25f * xm;
        if (lane < LDIM - 1)  v += 0.25f * xp;
        sLam[col * 32 + lane] = v;           // lane 31 stores dead pad
    }
    __syncthreads();

    // Phase B: 4-tap column resize + H multiply -> sP (stride 33).
    {
        const int l = lane, dc0 = warp;
        if (l < LDIM) {
            #pragma unroll
            for (int q = 0; q < 8; ++q) {
                int dc = dc0 + q * 8;            // 0..63
                int c = c0 + dc;
                float v;
                if (c == 0) {
                    v = (3.f/7.f)*sLam[1*32 + l] + (3.f/7.f)*sLam[2*32 + l]
                      + (1.f/7.f)*sLam[3*32 + l];
                } else if (c == MDIM - 1) {
                    v = (1.f/7.f)*sLam[126*32 + l] + (3.f/7.f)*sLam[127*32 + l]
                      + (3.f/7.f)*sLam[128*32 + l];
                } else {
                    int b = 2 * dc * 32 + l;
                    v = 0.125f*sLam[b]      + 0.375f*sLam[b + 32]
                      + 0.375f*sLam[b + 64] + 0.125f*sLam[b + 96];
                }
                sP[dc * 33 + l] = __ldg(Hr + c * LDIM + l) * v;
            }
        }
    }
    __syncthreads();

    // Phase D: skewed partial sums for this tile (deterministic, no atomics).
    if (tid < YLEN) {
        int lcc = tid;
        int ilo = lcc - (WC - 1); if (ilo < 0) ilo = 0;
        int ihi = (lcc < LDIM - 1) ? lcc : (LDIM - 1);
        float acc = 0.f;
        for (int i = ilo; i <= ihi; ++i)
            acc += sP[(lcc - i) * 33 + i];     // bank-conflict-free (stride 33)
        g_ynp[(t * MDIM + r) * YPAD + lcc] = acc;
    }
}

// ---------------------------------------------------------------------------
// Combine tile partials -> yn row + per-row max.
// ---------------------------------------------------------------------------
__global__ void __launch_bounds__(256) k_max(void) {
    __shared__ float sred[32];
    const int r = blockIdx.x, tid = threadIdx.x;
    float lmax = -INFINITY;
    for (int cc = tid; cc < CTOT; cc += 256) {
        int thi = cc >> 6; if (thi > NTILE - 1) thi = NTILE - 1;
        int tlo = (cc - 30) / 64; if (tlo < 0) tlo = 0;   // = max(0, ceil((cc-93)/64))
        float s = 0.f;
        for (int t2 = tlo; t2 <= thi; ++t2)
            s += __ldcs(&g_ynp[(t2 * MDIM + r) * YPAD + (cc - (t2 << 6))]);
        g_yn[r * CTOT + cc] = s;
        lmax = fmaxf(lmax, s);
    }
    float bm = blockReduceMax(lmax, sred);
    if (tid == 0) g_rmax1[r] = bm;
}

// Build zero-padded residual sE[0..CTOT+1] (sE[0]=sE[CTOT+1]=0, sE[1+c]=res[c])
// and its full lambda-conv s2[c] (zero-extended ends).
__device__ __forceinline__ void buildResidual(const float* __restrict__ y, int r,
                                              float invY, float* sE, float* s2) {
    const float* ynr = g_yn + r * CTOT;
    const float* yr  = y + r * CTOT;
    const int tid = threadIdx.x, nt = blockDim.x;
    if (tid == 0) { sE[0] = 0.f; sE[CTOT + 1] = 0.f; }
    for (int cc = tid; cc < CTOT; cc += nt)
        sE[cc + 1] = __ldcs(ynr + cc) * invY - __ldcs(yr + cc);
    __syncthreads();
    for (int cc = tid; cc < CTOT; cc += nt)
        s2[cc] = 0.25f * (sE[cc] + sE[cc + 2]) + 0.5f * sE[cc + 1];
    __syncthreads();
}

// X2 element: middle i -> s2[m+i]; boundary corrections are single
// predicated FMAs thanks to the zero pads in sE.
//   i==0:  v = s2[m]    - 0.25*sE[m]      (sE[m]    = res[m-1],  0 at m=0)
//   i==30: v = s2[m+30] - 0.25*sE[m+32]   (sE[m+32] = res[m+31], 0 at m=511)
__device__ __forceinline__ float x2val(const float* sE, const float* s2,
                                       int m, int i) {
    float v = s2[m + i];
    if (i == 0)        v -= 0.25f * sE[m];
    if (i == LDIM - 1) v -= 0.25f * sE[m + 32];
    return v;
}

// ---------------------------------------------------------------------------
// Backward pass 1: per-row max of X2 (H expected L2-resident from k_fwd).
// ---------------------------------------------------------------------------
__global__ void __launch_bounds__(512) k_bwd1(const float* __restrict__ y,
                                              const float* __restrict__ H) {
    __shared__ float sE[CTOT + 2];
    __shared__ float s2[CTOT];
    __shared__ float sred[32];
    const int r = blockIdx.x, tid = threadIdx.x;

    float v0 = (tid < MDIM) ? g_rmax1[tid] : -INFINITY;
    const float invY = 1.0f / blockReduceMax(v0, sred);
    buildResidual(y, r, invY, sE, s2);

    const float4* H4 = (const float4*)(H + (size_t)r * XCE);
    float lmax = -INFINITY;
    for (int j = tid; j < XC4; j += 512) {
        float4 h = __ldg(H4 + j);
        int e = j * 4;
        int m = e / LDIM, i = e - m * LDIM;
        float a0 = h.x * x2val(sE, s2, m, i);
        if (++i == LDIM) { i = 0; ++m; }
        float a1 = h.y * x2val(sE, s2, m, i);
        if (++i == LDIM) { i = 0; ++m; }
        float a2 = h.z * x2val(sE, s2, m, i);
        if (++i == LDIM) { i = 0; ++m; }
        float a3 = h.w * x2val(sE, s2, m, i);
        lmax = fmaxf(fmaxf(fmaxf(a0, a1), fmaxf(a2, a3)), lmax);
    }
    float bm = blockReduceMax(lmax, sred);
    if (tid == 0) g_rmax2[r] = bm;
}

// ---------------------------------------------------------------------------
// Backward pass 2: recompute X2 (H L2-resident), stream normalized output.
// ---------------------------------------------------------------------------
__global__ void __launch_bounds__(512) k_bwd2(const float* __restrict__ y,
                                              const float* __restrict__ H,
                                              float* __restrict__ out) {
    __shared__ float sE[CTOT + 2];
    __shared__ float s2[CTOT];
    __shared__ float sred[32];
    const int r = blockIdx.x, tid = threadIdx.x;

    float v0 = (tid < MDIM) ? g_rmax1[tid] : -INFINITY;
    const float invY = 1.0f / blockReduceMax(v0, sred);
    float v1 = (tid < MDIM) ? g_rmax2[tid] : -INFINITY;
    const float invO = 1.0f / blockReduceMax(v1, sred);
    buildResidual(y, r, invY, sE, s2);

    const float4* H4 = (const float4*)(H + (size_t)r * XCE);
    float4*       O4 = (float4*)(out + (size_t)r * XCE);
    for (int j = tid; j < XC4; j += 512) {
        float4 h = __ldg(H4 + j);
        int e = j * 4;
        int m = e / LDIM, i = e - m * LDIM;
        float4 o;
        o.x = h.x * x2val(sE, s2, m, i) * invO;
        if (++i == LDIM) { i = 0; ++m; }
        o.y = h.y * x2val(sE, s2, m, i) * invO;
        if (++i == LDIM) { i = 0; ++m; }
        o.z = h.z * x2val(sE, s2, m, i) * invO;
        if (++i == LDIM) { i = 0; ++m; }
        o.w = h.w * x2val(sE, s2, m, i) * invO;
        __stcs(O4 + j, o);                 // never re-read: bypass-ish L2
    }
}

extern "C" void kernel_launch(void* const* d_in, const int* in_sizes, int n_in,
                              void* d_out, int out_size) {
    const float *X = 0, *y = 0, *H = 0;
    for (int i = 0; i < n_in; ++i) {
        if      (in_sizes[i] == NX * NX * LDIM)     X = (const float*)d_in[i];
        else if (in_sizes[i] == MDIM * CTOT)        y = (const float*)d_in[i];
        else if (in_sizes[i] == MDIM * MDIM * LDIM) H = (const float*)d_in[i];
    }
    if (!X || !y || !H) {
        X = (const float*)d_in[0];
        y = (const float*)d_in[1];
        H = (const float*)d_in[2];
    }
    float* out = (float*)d_out;

    dim3 gf(NTILE, MDIM);
    k_fwd <<<gf, 256>>>(X, H);
    k_max <<<MDIM, 256>>>();
    k_bwd1<<<MDIM, 512>>>(y, H);
    k_bwd2<<<MDIM, 512>>>(y, H, out);
}